// round 11
// baseline (speedup 1.0000x reference)
#include <cuda_runtime.h>

#define NP 262144
#define GRIDW 256
#define NUM_CELLS (GRIDW*GRIDW)
#define KSLOT 32
#define CAP 32
#define MAXN 64
#define FULLM 0xffffffffu

// ---------------- scratch (device globals) ----------------------------------
__device__ float    g_partH[256];
__device__ float    g_partX[256];
__device__ float    g_partY[256];
__device__ int      g_cellCount[NUM_CELLS + 1];
__device__ float4   g_cellListP[NUM_CELLS * CAP];       // {bits(idx), x, y, pad}
__device__ int      g_tabCnt[NUM_CELLS + 1];
__device__ float4   g_tab[(NUM_CELLS + 1) * KSLOT];     // {bits(idx), x, y, pad}
__device__ float2   g_aux[NP];                          // {t = d2 threshold, rh = 1/h}

// ------- kernel 1: zero counts + per-block partial reductions ---------------
__global__ void initRedK(const float* __restrict__ pos, const float* __restrict__ sup) {
    int tid = blockIdx.x * blockDim.x + threadIdx.x;
    for (int c = tid; c <= NUM_CELLS; c += gridDim.x * blockDim.x)
        g_cellCount[c] = 0;
    if (tid == 0) g_tabCnt[NUM_CELLS] = 0;   // sentinel cell: always empty

    __shared__ float sH[256], sX[256], sY[256];
    float h = 0.0f, x = __int_as_float(0x7f800000), y = __int_as_float(0x7f800000);
    for (int i = tid; i < NP; i += gridDim.x * blockDim.x) {
        h = fmaxf(h, sup[i]);
        float2 p = ((const float2*)pos)[i];
        x = fminf(x, p.x);
        y = fminf(y, p.y);
    }
    int t = threadIdx.x;
    sH[t] = h; sX[t] = x; sY[t] = y;
    __syncthreads();
    for (int s = 128; s > 0; s >>= 1) {
        if (t < s) {
            sH[t] = fmaxf(sH[t], sH[t + s]);
            sX[t] = fminf(sX[t], sX[t + s]);
            sY[t] = fminf(sY[t], sY[t + s]);
        }
        __syncthreads();
    }
    if (t == 0) {
        g_partH[blockIdx.x] = sH[0];
        g_partX[blockIdx.x] = sX[0];
        g_partY[blockIdx.x] = sY[0];
    }
}

// ------- kernel 2: combine partials + bin particles + per-particle aux ------
__global__ void binK(const float* __restrict__ pos, const float* __restrict__ sup) {
    __shared__ float sH[256], sX[256], sY[256];
    int t = threadIdx.x;
    sH[t] = g_partH[t]; sX[t] = g_partX[t]; sY[t] = g_partY[t];
    __syncthreads();
    for (int s = 128; s > 0; s >>= 1) {
        if (t < s) {
            sH[t] = fmaxf(sH[t], sH[t + s]);
            sX[t] = fminf(sX[t], sX[t + s]);
            sY[t] = fminf(sY[t], sY[t + s]);
        }
        __syncthreads();
    }
    float hM = sH[0];
    float qx = sX[0] - hM;
    float qy = sY[0] - hM;

    int i = blockIdx.x * blockDim.x + threadIdx.x;
    if (i >= NP) return;
    float2 p = ((const float2*)pos)[i];
    int ix = (int)ceilf((p.x - qx) / hM);
    int iy = (int)ceilf((p.y - qy) / hM);
    ix = min(max(ix, 0), GRIDW - 1);
    iy = min(max(iy, 0), GRIDW - 1);
    int lin = ix + GRIDW * iy;
    int slot = atomicAdd(&g_cellCount[lin], 1);
    if (slot < CAP)
        g_cellListP[lin * CAP + slot] = make_float4(__int_as_float(i), p.x, p.y, 0.0f);

    // ---- per-particle: t = largest float with fl(sqrt(t)) <= h  (exact) ----
    float h = sup[i];
    float u = __fmul_rn(h, h);
    if (__fsqrt_rn(u) > h) u = __int_as_float(__float_as_int(u) - 1);
    if (__fsqrt_rn(u) > h) u = __int_as_float(__float_as_int(u) - 1);
    if (__fsqrt_rn(u) > h) u = __int_as_float(__float_as_int(u) - 1);
    float un = __int_as_float(__float_as_int(u) + 1);
    if (__fsqrt_rn(un) <= h) {
        u = un; un = __int_as_float(__float_as_int(u) + 1);
        if (__fsqrt_rn(un) <= h) {
            u = un; un = __int_as_float(__float_as_int(u) + 1);
            if (__fsqrt_rn(un) <= h) u = un;
        }
    }
    g_aux[i] = make_float2(u, __frcp_rn(h));
}

// ------- kernel 3: warp-per-cell rank sort (gather-free) --------------------
__global__ void sortK() {
    int w = (blockIdx.x * blockDim.x + threadIdx.x) >> 5;
    if (w >= NUM_CELLS) return;
    int lane = threadIdx.x & 31;
    int cnt = g_cellCount[w];
    int m = min(cnt, KSLOT);
    float4 e = make_float4(0.f, 0.f, 0.f, 0.f);
    int idx = 0x7fffffff;
    if (lane < m) {
        e = g_cellListP[w * CAP + lane];
        idx = __float_as_int(e.x);
    }
    int rank = 0;
    for (int j = 0; j < m; j++) {
        int v = __shfl_sync(FULLM, idx, j);
        rank += (v < idx);
    }
    if (lane == 0) g_tabCnt[w] = m;
    if (lane < m) g_tab[w * KSLOT + rank] = e;
}

__device__ __forceinline__ float sqrt_approx(float x) {
    float r;
    asm("sqrt.approx.f32 %0, %1;" : "=f"(r) : "f"(x));
    return r;
}

// ------- kernel 4: warp-per-cell neighbor search -----------------------------
__global__ void searchK(float* __restrict__ out) {
    __shared__ float4 sQ[8][32];      // per-warp query records {px, py, tq, rh}
    __shared__ int    sQb[8][32];     // per-warp query rbase (qid << 6)

    int w = (blockIdx.x * blockDim.x + threadIdx.x) >> 5;   // warp id = cell
    if (w >= NUM_CELLS) return;
    int lane = threadIdx.x & 31;
    int wid = (threadIdx.x >> 5) & 7;
    unsigned below = (1u << lane) - 1u;

    // ---- stencil setup (once per cell) ----
    int c = NUM_CELLS, m = 0;
    if (lane < 9) {
        int dxo = lane / 3 - 1;
        int dyo = lane % 3 - 1;
        int cc = w + dxo + GRIDW * dyo;
        cc = min(max(cc, 0), NUM_CELLS);
        c = cc;
        m = g_tabCnt[cc];
    }
    int incl = m;
#pragma unroll
    for (int d = 1; d < 16; d <<= 1) {
        int v = __shfl_up_sync(FULLM, incl, d);
        if (lane >= d) incl += v;
    }
    int pref = incl - m;
    int T = __shfl_sync(FULLM, incl, 8);

    int qcnt = __shfl_sync(FULLM, m, 4);      // center cell = this cell's queries
    if (qcnt == 0) return;

    int p1 = __shfl_sync(FULLM, pref, 1);
    int p2 = __shfl_sync(FULLM, pref, 2);
    int p3 = __shfl_sync(FULLM, pref, 3);
    int p4 = __shfl_sync(FULLM, pref, 4);
    int p5 = __shfl_sync(FULLM, pref, 5);
    int p6 = __shfl_sync(FULLM, pref, 6);
    int p7 = __shfl_sync(FULLM, pref, 7);
    int p8 = __shfl_sync(FULLM, pref, 8);

    // ---- query data: load + stage into smem ----
    int qidl = 0;
    if (lane < qcnt) {
        float4 qe = g_cellListP[w * CAP + lane];
        qidl = __float_as_int(qe.x);
        float2 aux = __ldg(&g_aux[qidl]);     // parallel prefetch {t, 1/h}
        sQ[wid][lane] = make_float4(qe.y, qe.z, aux.x, aux.y);
        sQb[wid][lane] = qidl << 6;
    }
    __syncwarp();

    // ---- preload candidates (chunks 0,1 cover T <= 64) ----
    float4 e0 = make_float4(0.f, 0.f, 0.f, 0.f);
    float4 e1 = make_float4(0.f, 0.f, 0.f, 0.f);
    bool act0 = lane < T;
    {
        int t = lane;
        int o = (t >= p1) + (t >= p2) + (t >= p3) + (t >= p4) +
                (t >= p5) + (t >= p6) + (t >= p7) + (t >= p8);
        int cc = __shfl_sync(FULLM, c, o);
        int po = __shfl_sync(FULLM, pref, o);
        if (act0) e0 = g_tab[cc * KSLOT + (t - po)];
    }
    bool act1 = (lane + 32) < T;
    if (T > 32) {
        int t = lane + 32;
        int o = (t >= p1) + (t >= p2) + (t >= p3) + (t >= p4) +
                (t >= p5) + (t >= p6) + (t >= p7) + (t >= p8);
        int cc = __shfl_sync(FULLM, c, o);
        int po = __shfl_sync(FULLM, pref, o);
        if (act1) e1 = g_tab[cc * KSLOT + (t - po)];
    }
    float n0 = (float)__float_as_int(e0.x);
    float n1 = (float)__float_as_int(e1.x);

    float* outN = out;                              // (N, 64) neighbor indices
    float* outC = out + (size_t)NP * MAXN;          // (N,)    counts
    float* outR = outC + NP;                        // (N, 64) radial

    int myCnt = 0;

    if (T <= 32) {
        // ======== one chunk: 32 lanes -> positions [0,32); fill [32,64) ======
        for (int q = 0; q < qcnt; q++) {
            float4 qd = sQ[wid][q];
            int  rbase = sQb[wid][q];
            float* pN = outN + rbase;
            float* pR = outR + rbase;

            float dx = __fsub_rn(e0.y, qd.x);
            float dy = __fsub_rn(e0.z, qd.y);
            float d2 = __fadd_rn(__fmul_rn(dx, dx), __fmul_rn(dy, dy));
            float rad = __fmul_rn(sqrt_approx(d2), qd.w);
            bool ok = act0 && (d2 <= qd.z);
            unsigned bal = __ballot_sync(FULLM, ok);
            int cnt = __popc(bal);
            int p = __popc(bal & below);
            int s = ok ? p : cnt + lane - p;        // unconditional slot in [0,32)
            pN[s] = ok ? n0 : -1.0f;
            pR[s] = ok ? rad : 0.0f;
            // fill [32,64): one STG.128 round
            if (lane < 8)
                ((float4*)(pN + 32))[lane] = make_float4(-1.f, -1.f, -1.f, -1.f);
            else if (lane < 16)
                ((float4*)(pR + 32))[lane - 8] = make_float4(0.f, 0.f, 0.f, 0.f);
            if (q == lane) myCnt = cnt;
        }
    } else if (T <= 64) {
        // ======== two chunks: 64 lane-slots -> positions [0,64) exactly =====
        for (int q = 0; q < qcnt; q++) {
            float4 qd = sQ[wid][q];
            int  rbase = sQb[wid][q];
            float* pN = outN + rbase;
            float* pR = outR + rbase;

            float dx0 = __fsub_rn(e0.y, qd.x);
            float dy0 = __fsub_rn(e0.z, qd.y);
            float d20 = __fadd_rn(__fmul_rn(dx0, dx0), __fmul_rn(dy0, dy0));
            float rad0 = __fmul_rn(sqrt_approx(d20), qd.w);
            bool ok0 = act0 && (d20 <= qd.z);

            float dx1 = __fsub_rn(e1.y, qd.x);
            float dy1 = __fsub_rn(e1.z, qd.y);
            float d21 = __fadd_rn(__fmul_rn(dx1, dx1), __fmul_rn(dy1, dy1));
            float rad1 = __fmul_rn(sqrt_approx(d21), qd.w);
            bool ok1 = act1 && (d21 <= qd.z);

            unsigned bal0 = __ballot_sync(FULLM, ok0);
            unsigned bal1 = __ballot_sync(FULLM, ok1);
            int c0 = __popc(bal0);
            int c1 = __popc(bal1);
            int cnt = c0 + c1;

            int q0 = __popc(bal0 & below);
            int s0 = ok0 ? q0 : cnt + lane - q0;            // ok:[0,c0) / fill:[cnt,cnt+32-c0)
            pN[s0] = ok0 ? n0 : -1.0f;
            pR[s0] = ok0 ? rad0 : 0.0f;

            int q1 = __popc(bal1 & below);
            int s1 = ok1 ? c0 + q1
                         : cnt + (32 - c0) + lane - q1;     // rest of [0,64)
            pN[s1] = ok1 ? n1 : -1.0f;
            pR[s1] = ok1 ? rad1 : 0.0f;

            if (q == lane) myCnt = cnt;
        }
    } else {
        // ======== rare T > 64: guarded path =================================
        for (int q = 0; q < qcnt; q++) {
            float4 qd = sQ[wid][q];
            int  rbase = sQb[wid][q];
            float px = qd.x, py = qd.y, tq = qd.z, rh = qd.w;
            float* pN = outN + rbase;
            float* pR = outR + rbase;

            int cnt;
            {
                float dx = __fsub_rn(e0.y, px);
                float dy = __fsub_rn(e0.z, py);
                float d2 = __fadd_rn(__fmul_rn(dx, dx), __fmul_rn(dy, dy));
                float rad = __fmul_rn(sqrt_approx(d2), rh);
                bool ok = act0 && (d2 <= tq);
                unsigned bal = __ballot_sync(FULLM, ok);
                int slot = __popc(bal & below);
                if (ok) { pN[slot] = n0; pR[slot] = rad; }
                cnt = __popc(bal);
            }
            {
                float dx = __fsub_rn(e1.y, px);
                float dy = __fsub_rn(e1.z, py);
                float d2 = __fadd_rn(__fmul_rn(dx, dx), __fmul_rn(dy, dy));
                float rad = __fmul_rn(sqrt_approx(d2), rh);
                bool ok = act1 && (d2 <= tq);
                unsigned bal = __ballot_sync(FULLM, ok);
                int slot = cnt + __popc(bal & below);
                if (ok) { pN[slot] = n1; pR[slot] = rad; }
                cnt += __popc(bal);
            }
            for (int tb = 64; tb < T; tb += 32) {
                int t = tb + lane;
                bool act = t < T;
                int o = (t >= p1) + (t >= p2) + (t >= p3) + (t >= p4) +
                        (t >= p5) + (t >= p6) + (t >= p7) + (t >= p8);
                int cc = __shfl_sync(FULLM, c, o);
                int po = __shfl_sync(FULLM, pref, o);
                float nidx = 0.0f, d2 = 0.0f;
                if (act) {
                    float4 e = g_tab[cc * KSLOT + (t - po)];
                    float dx = __fsub_rn(e.y, px);
                    float dy = __fsub_rn(e.z, py);
                    d2 = __fadd_rn(__fmul_rn(dx, dx), __fmul_rn(dy, dy));
                    nidx = (float)__float_as_int(e.x);
                }
                float rad = __fmul_rn(sqrt_approx(d2), rh);
                bool ok = act && (d2 <= tq);
                unsigned bal = __ballot_sync(FULLM, ok);
                int slot = cnt + __popc(bal & below);
                if (ok && slot < MAXN) { pN[slot] = nidx; pR[slot] = rad; }
                cnt += __popc(bal);
            }
            int start = min(cnt, MAXN);
            for (int k = start + lane; k < MAXN; k += 32) {
                pN[k] = -1.0f;
                pR[k] = 0.0f;
            }
            if (q == lane) myCnt = cnt;
        }
    }
    if (lane < qcnt) outC[qidl] = (float)myCnt;
}

// ---------------- launch ------------------------------------------------------
extern "C" void kernel_launch(void* const* d_in, const int* in_sizes, int n_in,
                              void* d_out, int out_size) {
    const float* pos = (const float*)d_in[0];   // (N, 2) float32
    const float* sup = (const float*)d_in[1];   // (N,)   float32
    float* out = (float*)d_out;

    initRedK<<<256, 256>>>(pos, sup);
    binK<<<NP / 256, 256>>>(pos, sup);
    sortK<<<(NUM_CELLS * 32) / 256, 256>>>();
    searchK<<<(NUM_CELLS * 32) / 256, 256>>>(out);
}

// round 12
// speedup vs baseline: 1.1299x; 1.1299x over previous
#include <cuda_runtime.h>

#define NP 262144
#define GRIDW 256
#define NUM_CELLS (GRIDW*GRIDW)
#define KSLOT 32
#define CAP 32
#define MAXN 64
#define FULLM 0xffffffffu

// ---------------- scratch (device globals) ----------------------------------
__device__ float    g_partH[256];
__device__ float    g_partX[256];
__device__ float    g_partY[256];
__device__ int      g_cellCount[NUM_CELLS + 1];
__device__ float4   g_cellListP[NUM_CELLS * CAP];       // {bits(idx), x, y, pad}
__device__ int      g_tabCnt[NUM_CELLS + 1];
__device__ float4   g_tab[(NUM_CELLS + 1) * KSLOT];     // {bits(idx), x, y, pad}
__device__ float2   g_aux[NP];                          // {t = d2 threshold, rh = 1/h}

// ------- kernel 1: zero counts + per-block partial reductions ---------------
__global__ void initRedK(const float* __restrict__ pos, const float* __restrict__ sup) {
    int tid = blockIdx.x * blockDim.x + threadIdx.x;
    for (int c = tid; c <= NUM_CELLS; c += gridDim.x * blockDim.x)
        g_cellCount[c] = 0;
    if (tid == 0) g_tabCnt[NUM_CELLS] = 0;   // sentinel cell: always empty

    __shared__ float sH[256], sX[256], sY[256];
    float h = 0.0f, x = __int_as_float(0x7f800000), y = __int_as_float(0x7f800000);
    for (int i = tid; i < NP; i += gridDim.x * blockDim.x) {
        h = fmaxf(h, sup[i]);
        float2 p = ((const float2*)pos)[i];
        x = fminf(x, p.x);
        y = fminf(y, p.y);
    }
    int t = threadIdx.x;
    sH[t] = h; sX[t] = x; sY[t] = y;
    __syncthreads();
    for (int s = 128; s > 0; s >>= 1) {
        if (t < s) {
            sH[t] = fmaxf(sH[t], sH[t + s]);
            sX[t] = fminf(sX[t], sX[t + s]);
            sY[t] = fminf(sY[t], sY[t + s]);
        }
        __syncthreads();
    }
    if (t == 0) {
        g_partH[blockIdx.x] = sH[0];
        g_partX[blockIdx.x] = sX[0];
        g_partY[blockIdx.x] = sY[0];
    }
}

// ------- kernel 2: combine partials + bin particles + per-particle aux ------
__global__ void binK(const float* __restrict__ pos, const float* __restrict__ sup) {
    __shared__ float sH[256], sX[256], sY[256];
    int t = threadIdx.x;
    sH[t] = g_partH[t]; sX[t] = g_partX[t]; sY[t] = g_partY[t];
    __syncthreads();
    for (int s = 128; s > 0; s >>= 1) {
        if (t < s) {
            sH[t] = fmaxf(sH[t], sH[t + s]);
            sX[t] = fminf(sX[t], sX[t + s]);
            sY[t] = fminf(sY[t], sY[t + s]);
        }
        __syncthreads();
    }
    float hM = sH[0];
    float qx = sX[0] - hM;
    float qy = sY[0] - hM;

    int i = blockIdx.x * blockDim.x + threadIdx.x;
    if (i >= NP) return;
    float2 p = ((const float2*)pos)[i];
    int ix = (int)ceilf((p.x - qx) / hM);
    int iy = (int)ceilf((p.y - qy) / hM);
    ix = min(max(ix, 0), GRIDW - 1);
    iy = min(max(iy, 0), GRIDW - 1);
    int lin = ix + GRIDW * iy;
    int slot = atomicAdd(&g_cellCount[lin], 1);
    if (slot < CAP)
        g_cellListP[lin * CAP + slot] = make_float4(__int_as_float(i), p.x, p.y, 0.0f);

    // ---- per-particle: t = largest float with fl(sqrt(t)) <= h  (exact) ----
    float h = sup[i];
    float u = __fmul_rn(h, h);
    if (__fsqrt_rn(u) > h) u = __int_as_float(__float_as_int(u) - 1);
    if (__fsqrt_rn(u) > h) u = __int_as_float(__float_as_int(u) - 1);
    if (__fsqrt_rn(u) > h) u = __int_as_float(__float_as_int(u) - 1);
    float un = __int_as_float(__float_as_int(u) + 1);
    if (__fsqrt_rn(un) <= h) {
        u = un; un = __int_as_float(__float_as_int(u) + 1);
        if (__fsqrt_rn(un) <= h) {
            u = un; un = __int_as_float(__float_as_int(u) + 1);
            if (__fsqrt_rn(un) <= h) u = un;
        }
    }
    g_aux[i] = make_float2(u, __frcp_rn(h));
}

// ------- kernel 3: warp-per-cell rank sort (gather-free) --------------------
__global__ void sortK() {
    int w = (blockIdx.x * blockDim.x + threadIdx.x) >> 5;
    if (w >= NUM_CELLS) return;
    int lane = threadIdx.x & 31;
    int cnt = g_cellCount[w];
    int m = min(cnt, KSLOT);
    float4 e = make_float4(0.f, 0.f, 0.f, 0.f);
    int idx = 0x7fffffff;
    if (lane < m) {
        e = g_cellListP[w * CAP + lane];
        idx = __float_as_int(e.x);
    }
    int rank = 0;
    for (int j = 0; j < m; j++) {
        int v = __shfl_sync(FULLM, idx, j);
        rank += (v < idx);
    }
    if (lane == 0) g_tabCnt[w] = m;
    if (lane < m) g_tab[w * KSLOT + rank] = e;
}

__device__ __forceinline__ float sqrt_approx(float x) {
    float r;
    asm("sqrt.approx.f32 %0, %1;" : "=f"(r) : "f"(x));
    return r;
}

// ------- kernel 4: warp-per-cell neighbor search -----------------------------
__global__ void searchK(float* __restrict__ out) {
    __shared__ float4 sQ[8][32];                  // query records {px, py, tq, rh}
    __shared__ int    sQb[8][32];                 // query rbase (qid << 6)
    __shared__ __align__(16) float sN[8][4][64];  // staged N rows (batch of 4)
    __shared__ __align__(16) float sR[8][4][64];  // staged R rows

    int w = (blockIdx.x * blockDim.x + threadIdx.x) >> 5;   // warp id = cell
    if (w >= NUM_CELLS) return;
    int lane = threadIdx.x & 31;
    int wid = (threadIdx.x >> 5) & 7;
    unsigned below = (1u << lane) - 1u;
    const float INF = __int_as_float(0x7f800000);

    // ---- stencil setup (once per cell) ----
    int c = NUM_CELLS, m = 0;
    if (lane < 9) {
        int dxo = lane / 3 - 1;
        int dyo = lane % 3 - 1;
        int cc = w + dxo + GRIDW * dyo;
        cc = min(max(cc, 0), NUM_CELLS);
        c = cc;
        m = g_tabCnt[cc];
    }
    int incl = m;
#pragma unroll
    for (int d = 1; d < 16; d <<= 1) {
        int v = __shfl_up_sync(FULLM, incl, d);
        if (lane >= d) incl += v;
    }
    int pref = incl - m;
    int T = __shfl_sync(FULLM, incl, 8);

    int qcnt = __shfl_sync(FULLM, m, 4);      // center cell = this cell's queries
    if (qcnt == 0) return;

    int p1 = __shfl_sync(FULLM, pref, 1);
    int p2 = __shfl_sync(FULLM, pref, 2);
    int p3 = __shfl_sync(FULLM, pref, 3);
    int p4 = __shfl_sync(FULLM, pref, 4);
    int p5 = __shfl_sync(FULLM, pref, 5);
    int p6 = __shfl_sync(FULLM, pref, 6);
    int p7 = __shfl_sync(FULLM, pref, 7);
    int p8 = __shfl_sync(FULLM, pref, 8);

    // ---- query data: load + stage into smem ----
    int qidl = 0;
    if (lane < qcnt) {
        float4 qe = g_cellListP[w * CAP + lane];
        qidl = __float_as_int(qe.x);
        float2 aux = __ldg(&g_aux[qidl]);     // parallel prefetch {t, 1/h}
        sQ[wid][lane] = make_float4(qe.y, qe.z, aux.x, aux.y);
        sQb[wid][lane] = qidl << 6;
    }
    __syncwarp();

    // ---- preload candidates, inf-padded for inactive lanes ----
    float4 e0 = make_float4(0.f, INF, INF, 0.f);
    float4 e1 = make_float4(0.f, INF, INF, 0.f);
    bool act0 = lane < T;
    {
        int t = lane;
        int o = (t >= p1) + (t >= p2) + (t >= p3) + (t >= p4) +
                (t >= p5) + (t >= p6) + (t >= p7) + (t >= p8);
        int cc = __shfl_sync(FULLM, c, o);
        int po = __shfl_sync(FULLM, pref, o);
        if (act0) e0 = g_tab[cc * KSLOT + (t - po)];
    }
    bool act1 = (lane + 32) < T;
    if (T > 32) {
        int t = lane + 32;
        int o = (t >= p1) + (t >= p2) + (t >= p3) + (t >= p4) +
                (t >= p5) + (t >= p6) + (t >= p7) + (t >= p8);
        int cc = __shfl_sync(FULLM, c, o);
        int po = __shfl_sync(FULLM, pref, o);
        if (act1) e1 = g_tab[cc * KSLOT + (t - po)];
    }
    float n0 = (float)__float_as_int(e0.x);
    float n1 = (float)__float_as_int(e1.x);

    float* outN = out;                              // (N, 64) neighbor indices
    float* outC = out + (size_t)NP * MAXN;          // (N,)    counts
    float* outR = outC + NP;                        // (N, 64) radial

    int myCnt = 0;

    // drain lane roles (fixed per thread)
    int half = lane >> 4;                           // 0 -> N row, 1 -> R row
    int sl   = (lane & 15) << 2;                    // float offset within row

    // ---- batched query processing ----
    for (int qb = 0; qb < qcnt; qb += 4) {
        // init stage: N rows = -1, R rows = 0 (4 vector STS rounds)
        float4* fN = (float4*)&sN[wid][0][0];
        float4* fR = (float4*)&sR[wid][0][0];
        fN[lane]      = make_float4(-1.f, -1.f, -1.f, -1.f);
        fN[lane + 32] = make_float4(-1.f, -1.f, -1.f, -1.f);
        fR[lane]      = make_float4(0.f, 0.f, 0.f, 0.f);
        fR[lane + 32] = make_float4(0.f, 0.f, 0.f, 0.f);
        __syncwarp();

        int nq = min(4, qcnt - qb);
        for (int qi = 0; qi < nq; qi++) {
            float4 qd = sQ[wid][qb + qi];
            float* rowN = sN[wid][qi];
            float* rowR = sR[wid][qi];

            int cnt;
            // chunk 0 (inf-padding makes act check unnecessary)
            {
                float dx = __fsub_rn(e0.y, qd.x);
                float dy = __fsub_rn(e0.z, qd.y);
                float d2 = __fadd_rn(__fmul_rn(dx, dx), __fmul_rn(dy, dy));
                float rad = __fmul_rn(sqrt_approx(d2), qd.w);
                bool ok = d2 <= qd.z;
                unsigned bal = __ballot_sync(FULLM, ok);
                int slot = __popc(bal & below);
                if (ok) {
                    rowN[slot] = n0;
                    rowR[slot] = rad;
                }
                cnt = __popc(bal);
            }
            // chunk 1
            if (T > 32) {
                float dx = __fsub_rn(e1.y, qd.x);
                float dy = __fsub_rn(e1.z, qd.y);
                float d2 = __fadd_rn(__fmul_rn(dx, dx), __fmul_rn(dy, dy));
                float rad = __fmul_rn(sqrt_approx(d2), qd.w);
                bool ok = d2 <= qd.z;
                unsigned bal = __ballot_sync(FULLM, ok);
                int slot = cnt + __popc(bal & below);
                if (ok) {
                    rowN[slot] = n1;
                    rowR[slot] = rad;
                }
                cnt += __popc(bal);
            }
            // rare: T > 64
            for (int tb = 64; tb < T; tb += 32) {
                int t = tb + lane;
                bool act = t < T;
                int o = (t >= p1) + (t >= p2) + (t >= p3) + (t >= p4) +
                        (t >= p5) + (t >= p6) + (t >= p7) + (t >= p8);
                int cc = __shfl_sync(FULLM, c, o);
                int po = __shfl_sync(FULLM, pref, o);
                float nidx = 0.0f, d2 = INF;
                if (act) {
                    float4 e = g_tab[cc * KSLOT + (t - po)];
                    float dx = __fsub_rn(e.y, qd.x);
                    float dy = __fsub_rn(e.z, qd.y);
                    d2 = __fadd_rn(__fmul_rn(dx, dx), __fmul_rn(dy, dy));
                    nidx = (float)__float_as_int(e.x);
                }
                float rad = __fmul_rn(sqrt_approx(d2), qd.w);
                bool ok = act && (d2 <= qd.z);
                unsigned bal = __ballot_sync(FULLM, ok);
                int slot = cnt + __popc(bal & below);
                if (ok && slot < MAXN) {
                    rowN[slot] = nidx;
                    rowR[slot] = rad;
                }
                cnt += __popc(bal);
            }
            if (qb + qi == lane) myCnt = cnt;
        }
        __syncwarp();

        // drain: one STG.128 round per query (lanes 0-15: N row, 16-31: R row)
        for (int qi = 0; qi < nq; qi++) {
            int rbase = sQb[wid][qb + qi];
            const float* src = half ? &sR[wid][qi][sl] : &sN[wid][qi][sl];
            float* dst = (half ? outR : outN) + (rbase + sl);
            __stcs((float4*)dst, *(const float4*)src);
        }
        __syncwarp();   // protect stage from next batch's re-init
    }
    if (lane < qcnt) __stcs(&outC[qidl], (float)myCnt);
}

// ---------------- launch ------------------------------------------------------
extern "C" void kernel_launch(void* const* d_in, const int* in_sizes, int n_in,
                              void* d_out, int out_size) {
    const float* pos = (const float*)d_in[0];   // (N, 2) float32
    const float* sup = (const float*)d_in[1];   // (N,)   float32
    float* out = (float*)d_out;

    initRedK<<<256, 256>>>(pos, sup);
    binK<<<NP / 256, 256>>>(pos, sup);
    sortK<<<(NUM_CELLS * 32) / 256, 256>>>();
    searchK<<<(NUM_CELLS * 32) / 256, 256>>>(out);
}